// round 13
// baseline (speedup 1.0000x reference)
#include <cuda_runtime.h>
#include <cuda_fp16.h>
#include <cstdint>

// ---------------------------------------------------------------------------
// HGCNLayer: two-hop mean aggregation over a bipartite graph.
//   rst  = segsum(h_src[edge_src] -> edge_dst) / max(deg_dst,1)
//   bsrc = segsum(rst[edge_dst]   -> edge_src) / max(deg_src,1)   (NORM_2=-1)
// Output layout: [bsrc (n_src x 128) | rst (n_dst x 128)]
//
// fp16 feature rows, fp32 accumulate, half-warp-per-edge gather.
// CSR build: rank-capturing degree kernel + single-launch lookback scan +
// atomic-free fill. Build kernels process 4 edges/thread with batched
// independent loads (MLP) to beat the scattered-access latency wall.
// ---------------------------------------------------------------------------

#define D_FEAT 128
#define MAXN   (1 << 21)
#define MAXE   (1 << 21)
#define SCAN_T 1024
#define MAXSRC (1 << 17)
#define MAXDST (1 << 16)

__device__ int g_cnt[2][MAXN];
__device__ int g_off[2][MAXN + 1];
__device__ int g_csr[2][MAXE];
__device__ int g_rank[2][MAXE];
__device__ unsigned long long g_state[2][2048];

__device__ __half g_h16[(size_t)MAXSRC * D_FEAT];   // fp16 h_src
__device__ __half g_r16[(size_t)MAXDST * D_FEAT];   // fp16 rst

// --- prep: fp32->fp16 convert of h_src, zero counters + scan state ---
__global__ void prep_kernel(const float* __restrict__ in, int n4,
                            int n_dst, int n_src) {
    int i = blockIdx.x * blockDim.x + threadIdx.x;
    if (i < n_dst) g_cnt[0][i] = 0;
    if (i < n_src) g_cnt[1][i] = 0;
    if (i < 2048) { g_state[0][i] = 0ull; g_state[1][i] = 0ull; }
    if (i >= n4) return;
    float4 v = __ldg(reinterpret_cast<const float4*>(in) + i);
    __half2 h0 = __float22half2_rn(make_float2(v.x, v.y));
    __half2 h1 = __float22half2_rn(make_float2(v.z, v.w));
    uint2 packed = make_uint2(*reinterpret_cast<uint32_t*>(&h0),
                              *reinterpret_cast<uint32_t*>(&h1));
    reinterpret_cast<uint2*>(g_h16)[i] = packed;
}

// --- degree + rank capture: 4 edges per thread, batched loads ---
__global__ void degree_kernel(const int* __restrict__ edge_src,
                              const int* __restrict__ edge_dst,
                              int n_edges) {
    int t      = blockIdx.x * blockDim.x + threadIdx.x;
    int stride = gridDim.x * blockDim.x;
    int e0 = t, e1 = t + stride, e2 = t + 2 * stride, e3 = t + 3 * stride;

    int s0, s1, s2, s3, d0, d1, d2, d3;
    if (e0 < n_edges) { s0 = edge_src[e0]; d0 = edge_dst[e0]; }
    if (e1 < n_edges) { s1 = edge_src[e1]; d1 = edge_dst[e1]; }
    if (e2 < n_edges) { s2 = edge_src[e2]; d2 = edge_dst[e2]; }
    if (e3 < n_edges) { s3 = edge_src[e3]; d3 = edge_dst[e3]; }

    int r0, r1, r2, r3;
    if (e0 < n_edges) r0 = atomicAdd(&g_cnt[0][d0], 1);
    if (e1 < n_edges) r1 = atomicAdd(&g_cnt[0][d1], 1);
    if (e2 < n_edges) r2 = atomicAdd(&g_cnt[0][d2], 1);
    if (e3 < n_edges) r3 = atomicAdd(&g_cnt[0][d3], 1);
    if (e0 < n_edges) g_rank[0][e0] = r0;
    if (e1 < n_edges) g_rank[0][e1] = r1;
    if (e2 < n_edges) g_rank[0][e2] = r2;
    if (e3 < n_edges) g_rank[0][e3] = r3;

    if (e0 < n_edges) r0 = atomicAdd(&g_cnt[1][s0], 1);
    if (e1 < n_edges) r1 = atomicAdd(&g_cnt[1][s1], 1);
    if (e2 < n_edges) r2 = atomicAdd(&g_cnt[1][s2], 1);
    if (e3 < n_edges) r3 = atomicAdd(&g_cnt[1][s3], 1);
    if (e0 < n_edges) g_rank[1][e0] = r0;
    if (e1 < n_edges) g_rank[1][e1] = r1;
    if (e2 < n_edges) g_rank[1][e2] = r2;
    if (e3 < n_edges) g_rank[1][e3] = r3;
}

// --- single-launch lookback scan over BOTH directions (blocks <= 148) ---
__global__ void __launch_bounds__(SCAN_T)
scan_fused(int nb0, int n_dst, int n_src) {
    __shared__ int sh[SCAN_T];
    __shared__ int red[32];
    int which = (blockIdx.x < nb0) ? 0 : 1;
    int blk   = (blockIdx.x < nb0) ? blockIdx.x : blockIdx.x - nb0;
    int n     = which ? n_src : n_dst;
    int t     = threadIdx.x;
    int i     = blk * SCAN_T + t;

    int v = (i < n) ? g_cnt[which][i] : 0;

    sh[t] = v;
    __syncthreads();
    for (int s = 1; s < SCAN_T; s <<= 1) {
        int u = (t >= s) ? sh[t - s] : 0;
        __syncthreads();
        sh[t] += u;
        __syncthreads();
    }
    int incl  = sh[t];
    int total = sh[SCAN_T - 1];

    if (t == 0) {
        unsigned long long st = (1ull << 62) | (unsigned int)total;
        atomicExch(&g_state[which][blk], st);
    }

    int part = 0;
    for (int p = t; p < blk; p += SCAN_T) {
        volatile unsigned long long* sp = &g_state[which][p];
        unsigned long long st;
        do { st = *sp; } while (!(st >> 62));
        part += (int)(unsigned int)(st & 0xffffffffu);
    }
    {
        int lane = t & 31, wrp = t >> 5;
        #pragma unroll
        for (int s = 16; s > 0; s >>= 1)
            part += __shfl_xor_sync(0xffffffffu, part, s);
        if (lane == 0) red[wrp] = part;
        __syncthreads();
        if (wrp == 0) {
            int x = red[lane];
            #pragma unroll
            for (int s = 16; s > 0; s >>= 1)
                x += __shfl_xor_sync(0xffffffffu, x, s);
            if (lane == 0) red[0] = x;
        }
        __syncthreads();
    }
    int base = red[0];

    if (i < n) {
        int ex = base + incl - v;
        g_off[which][i] = ex;
        if (i == n - 1) g_off[which][n] = ex + v;
    }
}

// --- atomic-free fill: 4 edges per thread, batched independent chains ---
__global__ void fill_kernel(const int* __restrict__ edge_src,
                            const int* __restrict__ edge_dst,
                            int n_edges) {
    int t      = blockIdx.x * blockDim.x + threadIdx.x;
    int stride = gridDim.x * blockDim.x;
    int e[4];
    #pragma unroll
    for (int k = 0; k < 4; k++) e[k] = t + k * stride;

    int s[4], d[4], ra[4], rb[4];
    #pragma unroll
    for (int k = 0; k < 4; k++)
        if (e[k] < n_edges) {
            s[k]  = edge_src[e[k]];
            d[k]  = edge_dst[e[k]];
            ra[k] = g_rank[0][e[k]];
            rb[k] = g_rank[1][e[k]];
        }

    int oa[4], ob[4];
    #pragma unroll
    for (int k = 0; k < 4; k++)
        if (e[k] < n_edges) {
            oa[k] = __ldg(&g_off[0][d[k]]);
            ob[k] = __ldg(&g_off[1][s[k]]);
        }

    #pragma unroll
    for (int k = 0; k < 4; k++)
        if (e[k] < n_edges) {
            g_csr[0][oa[k] + ra[k]] = s[k];
            g_csr[1][ob[k] + rb[k]] = d[k];
        }
}

// --- half-warp-per-edge fp16 gather: 2 edges per warp step via LDG.128. ---
__device__ __forceinline__ void accum8(const __half* __restrict__ feat,
                                       int id, int sub, bool valid,
                                       float* acc) {
    uint4 v = __ldg(reinterpret_cast<const uint4*>(
                        feat + (size_t)id * D_FEAT) + sub);
    if (valid) {
        __half2 h; float2 f;
        h = *reinterpret_cast<__half2*>(&v.x); f = __half22float2(h);
        acc[0] += f.x; acc[1] += f.y;
        h = *reinterpret_cast<__half2*>(&v.y); f = __half22float2(h);
        acc[2] += f.x; acc[3] += f.y;
        h = *reinterpret_cast<__half2*>(&v.z); f = __half22float2(h);
        acc[4] += f.x; acc[5] += f.y;
        h = *reinterpret_cast<__half2*>(&v.w); f = __half22float2(h);
        acc[6] += f.x; acc[7] += f.y;
    }
}

__global__ void gather_kernel(int which,
                              float* __restrict__ out,
                              int n_nodes) {
    int gtid = blockIdx.x * blockDim.x + threadIdx.x;
    int w    = gtid >> 5;
    int lane = threadIdx.x & 31;
    int half = lane >> 4;
    int sub  = lane & 15;
    if (w >= n_nodes) return;

    const __half* feat = which ? g_r16 : g_h16;
    const int* off = g_off[which];
    const int* csr = g_csr[which];

    int beg = off[w];
    int end = off[w + 1];
    int deg = end - beg;
    int safe = (deg > 0) ? csr[beg] : 0;

    float acc[8];
    #pragma unroll
    for (int i = 0; i < 8; i++) acc[i] = 0.f;

    int j = beg;
    for (; j + 8 <= end; j += 8) {
        #pragma unroll
        for (int p = 0; p < 4; p++)
            accum8(feat, csr[j + 2 * p + half], sub, true, acc);
    }
    for (; j + 2 <= end; j += 2)
        accum8(feat, csr[j + half], sub, true, acc);
    if (j < end) {
        int id = (half == 0) ? csr[j] : safe;
        accum8(feat, id, sub, half == 0, acc);
    }

    #pragma unroll
    for (int i = 0; i < 8; i++)
        acc[i] += __shfl_xor_sync(0xffffffffu, acc[i], 16);

    float inv = 1.0f / (float)(deg > 0 ? deg : 1);
    #pragma unroll
    for (int i = 0; i < 8; i++) acc[i] *= inv;

    if (half == 0) {
        float4* o = reinterpret_cast<float4*>(out + (size_t)w * D_FEAT) + 2 * sub;
        o[0] = make_float4(acc[0], acc[1], acc[2], acc[3]);
        o[1] = make_float4(acc[4], acc[5], acc[6], acc[7]);
    } else if (which == 0) {
        __half2 h0 = __float22half2_rn(make_float2(acc[0], acc[1]));
        __half2 h1 = __float22half2_rn(make_float2(acc[2], acc[3]));
        __half2 h2 = __float22half2_rn(make_float2(acc[4], acc[5]));
        __half2 h3 = __float22half2_rn(make_float2(acc[6], acc[7]));
        uint4 packed = make_uint4(*reinterpret_cast<uint32_t*>(&h0),
                                  *reinterpret_cast<uint32_t*>(&h1),
                                  *reinterpret_cast<uint32_t*>(&h2),
                                  *reinterpret_cast<uint32_t*>(&h3));
        reinterpret_cast<uint4*>(g_r16 + (size_t)w * D_FEAT)[sub] = packed;
    }
}

extern "C" void kernel_launch(void* const* d_in, const int* in_sizes, int n_in,
                              void* d_out, int out_size) {
    const float* h_src    = (const float*)d_in[0];
    const int*   edge_src = (const int*)d_in[1];
    const int*   edge_dst = (const int*)d_in[2];

    const int n_src   = in_sizes[0] / D_FEAT;
    const int n_edges = in_sizes[1];
    const int n_dst   = out_size / D_FEAT - n_src;

    float* bsrc = (float*)d_out;                          // [n_src, 128]
    float* rst  = (float*)d_out + (size_t)n_src * D_FEAT; // [n_dst, 128]

    const int nb0 = (n_dst + SCAN_T - 1) / SCAN_T;
    const int nb1 = (n_src + SCAN_T - 1) / SCAN_T;
    // edge kernels: 4 edges per thread
    const int EB4 = (n_edges / 4 + 255) / 256 + 1;

    // 0) convert h_src to fp16 + zero counters/scan-state
    {
        int n4 = n_src * (D_FEAT / 4);
        int mx = n4;
        if (n_dst > mx) mx = n_dst;
        if (n_src > mx) mx = n_src;
        if (2048 > mx)  mx = 2048;
        prep_kernel<<<(mx + 255) / 256, 256>>>(h_src, n4, n_dst, n_src);
    }

    // 1) CSR build
    degree_kernel<<<EB4, 256>>>(edge_src, edge_dst, n_edges);
    scan_fused<<<nb0 + nb1, SCAN_T>>>(nb0, n_dst, n_src);
    fill_kernel<<<EB4, 256>>>(edge_src, edge_dst, n_edges);

    // 2) forward: rst = mean over incoming src rows (also emits fp16 rst)
    {
        long long thr = (long long)n_dst * 32;
        gather_kernel<<<(int)((thr + 255) / 256), 256>>>(0, rst, n_dst);
    }

    // 3) backward: bsrc = mean over incoming rst rows (NORM_2 = -1)
    {
        long long thr = (long long)n_src * 32;
        gather_kernel<<<(int)((thr + 255) / 256), 256>>>(1, bsrc, n_src);
    }
}

// round 14
// speedup vs baseline: 1.0233x; 1.0233x over previous
#include <cuda_runtime.h>
#include <cuda_fp16.h>
#include <cstdint>

// ---------------------------------------------------------------------------
// HGCNLayer: two-hop mean aggregation over a bipartite graph.
//   rst  = segsum(h_src[edge_src] -> edge_dst) / max(deg_dst,1)
//   bsrc = segsum(rst[edge_dst]   -> edge_src) / max(deg_src,1)   (NORM_2=-1)
// Output layout: [bsrc (n_src x 128) | rst (n_dst x 128)]
//
// fp16 feature rows, fp32 accumulate, half-warp-per-edge gather.
// CSR build: rank-capturing degree (packed int2 ranks) + single-launch
// lookback scan + atomic-free fill (1 edge/thread: L2-sector-bound, R13
// showed batching hurts). fp16 convert overlapped on a second stream.
// ---------------------------------------------------------------------------

#define D_FEAT 128
#define MAXN   (1 << 21)
#define MAXE   (1 << 21)
#define SCAN_T 1024
#define MAXSRC (1 << 17)
#define MAXDST (1 << 16)

__device__ int  g_cnt[2][MAXN];
__device__ int  g_off[2][MAXN + 1];
__device__ int  g_csr[2][MAXE];
__device__ int2 g_rank2[MAXE];       // (rank in dir0, rank in dir1) per edge
__device__ unsigned long long g_state[2][2048];

__device__ __half g_h16[(size_t)MAXSRC * D_FEAT];   // fp16 h_src
__device__ __half g_r16[(size_t)MAXDST * D_FEAT];   // fp16 rst

// --- zero counters + scan state (tiny; must precede degree) ---
__global__ void zero_kernel(int n_dst, int n_src) {
    int i = blockIdx.x * blockDim.x + threadIdx.x;
    if (i < n_dst) g_cnt[0][i] = 0;
    if (i < n_src) g_cnt[1][i] = 0;
    if (i < 2048) { g_state[0][i] = 0ull; g_state[1][i] = 0ull; }
}

// --- fp32 -> fp16 convert of h_src (independent of CSR build; overlapped) ---
__global__ void convert_kernel(const float* __restrict__ in, int n4) {
    int i = blockIdx.x * blockDim.x + threadIdx.x;
    if (i >= n4) return;
    float4 v = __ldg(reinterpret_cast<const float4*>(in) + i);
    __half2 h0 = __float22half2_rn(make_float2(v.x, v.y));
    __half2 h1 = __float22half2_rn(make_float2(v.z, v.w));
    uint2 packed = make_uint2(*reinterpret_cast<uint32_t*>(&h0),
                              *reinterpret_cast<uint32_t*>(&h1));
    reinterpret_cast<uint2*>(g_h16)[i] = packed;
}

// --- degree + rank capture: one thread per edge, packed int2 rank store ---
__global__ void degree_kernel(const int* __restrict__ edge_src,
                              const int* __restrict__ edge_dst,
                              int n_edges) {
    int e = blockIdx.x * blockDim.x + threadIdx.x;
    if (e < n_edges) {
        int s = edge_src[e];
        int d = edge_dst[e];
        int r0 = atomicAdd(&g_cnt[0][d], 1);
        int r1 = atomicAdd(&g_cnt[1][s], 1);
        g_rank2[e] = make_int2(r0, r1);
    }
}

// --- single-launch lookback scan over BOTH directions (blocks <= 148) ---
__global__ void __launch_bounds__(SCAN_T)
scan_fused(int nb0, int n_dst, int n_src) {
    __shared__ int sh[SCAN_T];
    __shared__ int red[32];
    int which = (blockIdx.x < nb0) ? 0 : 1;
    int blk   = (blockIdx.x < nb0) ? blockIdx.x : blockIdx.x - nb0;
    int n     = which ? n_src : n_dst;
    int t     = threadIdx.x;
    int i     = blk * SCAN_T + t;

    int v = (i < n) ? g_cnt[which][i] : 0;

    sh[t] = v;
    __syncthreads();
    for (int s = 1; s < SCAN_T; s <<= 1) {
        int u = (t >= s) ? sh[t - s] : 0;
        __syncthreads();
        sh[t] += u;
        __syncthreads();
    }
    int incl  = sh[t];
    int total = sh[SCAN_T - 1];

    if (t == 0) {
        unsigned long long st = (1ull << 62) | (unsigned int)total;
        atomicExch(&g_state[which][blk], st);
    }

    int part = 0;
    for (int p = t; p < blk; p += SCAN_T) {
        volatile unsigned long long* sp = &g_state[which][p];
        unsigned long long st;
        do { st = *sp; } while (!(st >> 62));
        part += (int)(unsigned int)(st & 0xffffffffu);
    }
    {
        int lane = t & 31, wrp = t >> 5;
        #pragma unroll
        for (int s = 16; s > 0; s >>= 1)
            part += __shfl_xor_sync(0xffffffffu, part, s);
        if (lane == 0) red[wrp] = part;
        __syncthreads();
        if (wrp == 0) {
            int x = red[lane];
            #pragma unroll
            for (int s = 16; s > 0; s >>= 1)
                x += __shfl_xor_sync(0xffffffffu, x, s);
            if (lane == 0) red[0] = x;
        }
        __syncthreads();
    }
    int base = red[0];

    if (i < n) {
        int ex = base + incl - v;
        g_off[which][i] = ex;
        if (i == n - 1) g_off[which][n] = ex + v;
    }
}

// --- atomic-free fill: one thread per edge (L2-sector-bound; keep lean) ---
__global__ void fill_kernel(const int* __restrict__ edge_src,
                            const int* __restrict__ edge_dst,
                            int n_edges) {
    int e = blockIdx.x * blockDim.x + threadIdx.x;
    if (e < n_edges) {
        int s = edge_src[e];
        int d = edge_dst[e];
        int2 r = g_rank2[e];
        g_csr[0][__ldg(&g_off[0][d]) + r.x] = s;
        g_csr[1][__ldg(&g_off[1][s]) + r.y] = d;
    }
}

// --- half-warp-per-edge fp16 gather: 2 edges per warp step via LDG.128. ---
__device__ __forceinline__ void accum8(const __half* __restrict__ feat,
                                       int id, int sub, bool valid,
                                       float* acc) {
    uint4 v = __ldg(reinterpret_cast<const uint4*>(
                        feat + (size_t)id * D_FEAT) + sub);
    if (valid) {
        __half2 h; float2 f;
        h = *reinterpret_cast<__half2*>(&v.x); f = __half22float2(h);
        acc[0] += f.x; acc[1] += f.y;
        h = *reinterpret_cast<__half2*>(&v.y); f = __half22float2(h);
        acc[2] += f.x; acc[3] += f.y;
        h = *reinterpret_cast<__half2*>(&v.z); f = __half22float2(h);
        acc[4] += f.x; acc[5] += f.y;
        h = *reinterpret_cast<__half2*>(&v.w); f = __half22float2(h);
        acc[6] += f.x; acc[7] += f.y;
    }
}

__global__ void gather_kernel(int which,
                              float* __restrict__ out,
                              int n_nodes) {
    int gtid = blockIdx.x * blockDim.x + threadIdx.x;
    int w    = gtid >> 5;
    int lane = threadIdx.x & 31;
    int half = lane >> 4;
    int sub  = lane & 15;
    if (w >= n_nodes) return;

    const __half* feat = which ? g_r16 : g_h16;
    const int* off = g_off[which];
    const int* csr = g_csr[which];

    int beg = off[w];
    int end = off[w + 1];
    int deg = end - beg;
    int safe = (deg > 0) ? csr[beg] : 0;

    float acc[8];
    #pragma unroll
    for (int i = 0; i < 8; i++) acc[i] = 0.f;

    int j = beg;
    for (; j + 8 <= end; j += 8) {
        #pragma unroll
        for (int p = 0; p < 4; p++)
            accum8(feat, csr[j + 2 * p + half], sub, true, acc);
    }
    for (; j + 2 <= end; j += 2)
        accum8(feat, csr[j + half], sub, true, acc);
    if (j < end) {
        int id = (half == 0) ? csr[j] : safe;
        accum8(feat, id, sub, half == 0, acc);
    }

    #pragma unroll
    for (int i = 0; i < 8; i++)
        acc[i] += __shfl_xor_sync(0xffffffffu, acc[i], 16);

    float inv = 1.0f / (float)(deg > 0 ? deg : 1);
    #pragma unroll
    for (int i = 0; i < 8; i++) acc[i] *= inv;

    if (half == 0) {
        float4* o = reinterpret_cast<float4*>(out + (size_t)w * D_FEAT) + 2 * sub;
        o[0] = make_float4(acc[0], acc[1], acc[2], acc[3]);
        o[1] = make_float4(acc[4], acc[5], acc[6], acc[7]);
    } else if (which == 0) {
        __half2 h0 = __float22half2_rn(make_float2(acc[0], acc[1]));
        __half2 h1 = __float22half2_rn(make_float2(acc[2], acc[3]));
        __half2 h2 = __float22half2_rn(make_float2(acc[4], acc[5]));
        __half2 h3 = __float22half2_rn(make_float2(acc[6], acc[7]));
        uint4 packed = make_uint4(*reinterpret_cast<uint32_t*>(&h0),
                                  *reinterpret_cast<uint32_t*>(&h1),
                                  *reinterpret_cast<uint32_t*>(&h2),
                                  *reinterpret_cast<uint32_t*>(&h3));
        reinterpret_cast<uint4*>(g_r16 + (size_t)w * D_FEAT)[sub] = packed;
    }
}

extern "C" void kernel_launch(void* const* d_in, const int* in_sizes, int n_in,
                              void* d_out, int out_size) {
    const float* h_src    = (const float*)d_in[0];
    const int*   edge_src = (const int*)d_in[1];
    const int*   edge_dst = (const int*)d_in[2];

    const int n_src   = in_sizes[0] / D_FEAT;
    const int n_edges = in_sizes[1];
    const int n_dst   = out_size / D_FEAT - n_src;

    float* bsrc = (float*)d_out;                          // [n_src, 128]
    float* rst  = (float*)d_out + (size_t)n_src * D_FEAT; // [n_dst, 128]

    const int nb0 = (n_dst + SCAN_T - 1) / SCAN_T;
    const int nb1 = (n_src + SCAN_T - 1) / SCAN_T;
    const int EB  = (n_edges + 255) / 256;

    // second stream: fp16 convert overlaps the CSR build
    cudaStream_t s1;
    cudaStreamCreateWithFlags(&s1, cudaStreamNonBlocking);
    cudaEvent_t evFork, evConv;
    cudaEventCreateWithFlags(&evFork, cudaEventDisableTiming);
    cudaEventCreateWithFlags(&evConv, cudaEventDisableTiming);

    cudaEventRecord(evFork, 0);
    cudaStreamWaitEvent(s1, evFork, 0);
    {
        int n4 = n_src * (D_FEAT / 4);
        convert_kernel<<<(n4 + 255) / 256, 256, 0, s1>>>(h_src, n4);
    }
    cudaEventRecord(evConv, s1);

    // CSR build on the default stream
    {
        int mx = (n_src > n_dst) ? n_src : n_dst;
        if (2048 > mx) mx = 2048;
        zero_kernel<<<(mx + 255) / 256, 256>>>(n_dst, n_src);
    }
    degree_kernel<<<EB, 256>>>(edge_src, edge_dst, n_edges);
    scan_fused<<<nb0 + nb1, SCAN_T>>>(nb0, n_dst, n_src);
    fill_kernel<<<EB, 256>>>(edge_src, edge_dst, n_edges);

    // join: gather0 needs both the CSR and the fp16 h_src
    cudaStreamWaitEvent(0, evConv, 0);

    // forward: rst = mean over incoming src rows (also emits fp16 rst)
    {
        long long thr = (long long)n_dst * 32;
        gather_kernel<<<(int)((thr + 255) / 256), 256>>>(0, rst, n_dst);
    }

    // backward: bsrc = mean over incoming rst rows (NORM_2 = -1)
    {
        long long thr = (long long)n_src * 32;
        gather_kernel<<<(int)((thr + 255) / 256), 256>>>(1, bsrc, n_src);
    }

    cudaEventDestroy(evFork);
    cudaEventDestroy(evConv);
    cudaStreamDestroy(s1);
}